// round 17
// baseline (speedup 1.0000x reference)
#include <cuda_runtime.h>
#include <cuda_fp16.h>
#include <cstdint>

// ---------------------------------------------------------------------------
// TriangleAttention  N=256, D=128, H=4, DH=32 — fp16, ldmatrix operand loads
//
// 0: wconv: 5 weight matrices fp32 -> fp16
// 1: LayerNorm -> g_hn fp16 ; tri_bias fp16
// 2: proj GEMM (fp16 mma + LDSM)
// 3: flash attention, no max-tracking, full K/V resident, LDSM loads
// 4: out GEMM (fp16 mma + LDSM, fp32 out)
// ---------------------------------------------------------------------------

#define NN    256
#define DD    128
#define HH    4
#define DHH   32
#define MM    (NN * NN)

#define ASTRH 136
#define PROJ_SMEM_BYTES (3 * 128 * ASTRH * 2)   // 104448
#define OUT_SMEM_BYTES  (2 * 128 * ASTRH * 2)   //  69632

__device__ __half g_hn[MM * DD];
__device__ __half g_P[MM * 512];
__device__ __half g_bias[HH * MM];
__device__ __half g_O[MM * DD];
__device__ __half g_Wc[5][DD * DD];

// ---------------------------------------------------------------------------
__device__ __forceinline__ void mma_f16(float* d, const uint32_t* a, const uint32_t* b) {
    asm volatile(
        "mma.sync.aligned.m16n8k16.row.col.f32.f16.f16.f32 "
        "{%0,%1,%2,%3}, {%4,%5,%6,%7}, {%8,%9}, {%0,%1,%2,%3};\n"
        : "+f"(d[0]), "+f"(d[1]), "+f"(d[2]), "+f"(d[3])
        : "r"(a[0]), "r"(a[1]), "r"(a[2]), "r"(a[3]),
          "r"(b[0]), "r"(b[1]));
}

__device__ __forceinline__ void ldsm_x4(uint32_t* r, uint32_t addr) {
    asm volatile("ldmatrix.sync.aligned.m8n8.x4.shared.b16 {%0,%1,%2,%3}, [%4];"
        : "=r"(r[0]), "=r"(r[1]), "=r"(r[2]), "=r"(r[3]) : "r"(addr));
}

__device__ __forceinline__ uint32_t pack_h2(float a, float b) {
    __half2 h = __floats2half2_rn(a, b);
    return *(uint32_t*)&h;
}

__device__ __forceinline__ void cp_async16(uint32_t smem_addr, const void* gptr) {
    asm volatile("cp.async.ca.shared.global [%0], [%1], 16;\n"
                 :: "r"(smem_addr), "l"(gptr));
}
__device__ __forceinline__ void cp_async_commit() {
    asm volatile("cp.async.commit_group;\n");
}
__device__ __forceinline__ void cp_async_wait0() {
    asm volatile("cp.async.wait_group 0;\n");
}
__device__ __forceinline__ uint32_t smem_u32(const void* p) {
    return (uint32_t)__cvta_generic_to_shared(p);
}

// ---------------------------------------------------------------------------
// Kernel 0: weight conversion fp32 -> fp16.
// ---------------------------------------------------------------------------
__global__ void __launch_bounds__(256) wconv_kernel(
    const float* __restrict__ q_w, const float* __restrict__ k_w,
    const float* __restrict__ v_w, const float* __restrict__ g_w,
    const float* __restrict__ o_w)
{
    const float* src = (blockIdx.y == 0) ? q_w : (blockIdx.y == 1) ? k_w :
                       (blockIdx.y == 2) ? v_w : (blockIdx.y == 3) ? g_w : o_w;
    int idx = (blockIdx.x * 256 + threadIdx.x) * 4;
    float4 v = *(const float4*)&src[idx];
    __half h4[4];
    h4[0] = __float2half_rn(v.x); h4[1] = __float2half_rn(v.y);
    h4[2] = __float2half_rn(v.z); h4[3] = __float2half_rn(v.w);
    *(uint2*)&g_Wc[blockIdx.y][idx] = *(uint2*)h4;
}

// ---------------------------------------------------------------------------
// Kernel 1: LayerNorm + triangle bias (fp16 outputs).
// ---------------------------------------------------------------------------
__global__ void __launch_bounds__(256) ln_bias_kernel(
    const float* __restrict__ x, const float* __restrict__ ln_w,
    const float* __restrict__ ln_b, const float* __restrict__ bias_w)
{
    __shared__ float bw[4 * DD];
    int tid = threadIdx.x;
    bw[tid]       = bias_w[tid];
    bw[tid + 256] = bias_w[tid + 256];
    __syncthreads();

    int warp = tid >> 5, lane = tid & 31;
    int m = blockIdx.x * 8 + warp;

    const float4 v = *(const float4*)&x[(size_t)m * DD + lane * 4];
    float s = v.x + v.y + v.z + v.w;
    #pragma unroll
    for (int o = 16; o; o >>= 1) s += __shfl_xor_sync(0xffffffffu, s, o);
    const float mu = s * (1.0f / 128.0f);

    float d0 = v.x - mu, d1 = v.y - mu, d2 = v.z - mu, d3 = v.w - mu;
    float ss = d0 * d0 + d1 * d1 + d2 * d2 + d3 * d3;
    #pragma unroll
    for (int o = 16; o; o >>= 1) ss += __shfl_xor_sync(0xffffffffu, ss, o);
    const float rstd = rsqrtf(ss * (1.0f / 128.0f) + 1e-5f);

    const float4 w4 = *(const float4*)&ln_w[lane * 4];
    const float4 b4 = *(const float4*)&ln_b[lane * 4];
    float h0 = d0 * rstd * w4.x + b4.x;
    float h1 = d1 * rstd * w4.y + b4.y;
    float h2 = d2 * rstd * w4.z + b4.z;
    float h3 = d3 * rstd * w4.w + b4.w;

    __half h4[4];
    h4[0] = __float2half_rn(h0); h4[1] = __float2half_rn(h1);
    h4[2] = __float2half_rn(h2); h4[3] = __float2half_rn(h3);
    *(uint2*)&g_hn[(size_t)m * DD + lane * 4] = *(uint2*)h4;

    #pragma unroll
    for (int hh = 0; hh < 4; ++hh) {
        const float* bwr = &bw[hh * DD + lane * 4];
        float dot = h0 * bwr[0] + h1 * bwr[1] + h2 * bwr[2] + h3 * bwr[3];
        #pragma unroll
        for (int o = 16; o; o >>= 1) dot += __shfl_xor_sync(0xffffffffu, dot, o);
        if (lane == 0) g_bias[hh * MM + m] = __float2half_rn(dot);
    }
}

// ---------------------------------------------------------------------------
// fp16 GEMM core with ldmatrix fragment loads.
// ---------------------------------------------------------------------------
struct GemmCtx { int tid, lane, gid, tig, wm, wn; };

__device__ __forceinline__ void cp_tile_f16(__half* dst, const __half* __restrict__ src,
                                            size_t row_stride, int tid)
{
    #pragma unroll
    for (int l = 0; l < 8; ++l) {
        int fidx = tid + l * 256;
        int r  = fidx >> 4;
        int c8 = (fidx & 15) * 8;
        cp_async16(smem_u32(&dst[r * ASTRH + c8]), &src[(size_t)r * row_stride + c8]);
    }
}

__device__ __forceinline__ void gemm_mma_all(
    const __half* As, const __half* Bs, const GemmCtx& c, float acc[2][8][4])
{
    #pragma unroll
    for (int i = 0; i < 2; ++i)
        #pragma unroll
        for (int j = 0; j < 8; ++j)
            #pragma unroll
            for (int r = 0; r < 4; ++r) acc[i][j][r] = 0.0f;

    const int l15 = c.lane & 15, lhi = (c.lane >> 4);      // A addressing
    const int l7  = c.lane & 7,  lb8 = (c.lane >> 3) & 1;  // B addressing

    #pragma unroll
    for (int kc = 0; kc < 8; ++kc) {
        uint32_t af[2][4], bf[8][2];
        #pragma unroll
        for (int i = 0; i < 2; ++i)
            ldsm_x4(af[i], smem_u32(
                &As[(c.wm + i * 16 + l15) * ASTRH + kc * 16 + lhi * 8]));
        #pragma unroll
        for (int jp = 0; jp < 4; ++jp) {
            uint32_t t[4];
            ldsm_x4(t, smem_u32(
                &Bs[(c.wn + jp * 16 + lhi * 8 + l7) * ASTRH + kc * 16 + lb8 * 8]));
            bf[2 * jp][0] = t[0]; bf[2 * jp][1] = t[1];
            bf[2 * jp + 1][0] = t[2]; bf[2 * jp + 1][1] = t[3];
        }
        #pragma unroll
        for (int i = 0; i < 2; ++i)
            #pragma unroll
            for (int j = 0; j < 8; ++j)
                mma_f16(acc[i][j], af[i], bf[j]);
    }
}

// proj: A resident; B double-buffered.
__global__ void __launch_bounds__(256, 2) proj_gemm_f16()
{
    extern __shared__ __half hsm[];
    __half* As = hsm;
    __half* Bs0 = hsm + 128 * ASTRH;
    __half* Bs1 = hsm + 2 * 128 * ASTRH;

    const int m0 = blockIdx.x * 128;
    GemmCtx c;
    c.tid = threadIdx.x;
    c.lane = c.tid & 31;
    int wid = c.tid >> 5;
    c.gid = c.lane >> 2; c.tig = c.lane & 3;
    c.wm = (wid & 3) * 32; c.wn = (wid >> 2) * 64;

    cp_tile_f16(As, &g_hn[(size_t)m0 * 128], 128, c.tid);
    cp_tile_f16(Bs0, g_Wc[0], 128, c.tid);
    cp_async_commit();
    cp_async_wait0();
    __syncthreads();

    #pragma unroll
    for (int wsel = 0; wsel < 4; ++wsel) {
        __half* Bcur = (wsel & 1) ? Bs1 : Bs0;
        if (wsel < 3) {
            __half* Bnxt = (wsel & 1) ? Bs0 : Bs1;
            cp_tile_f16(Bnxt, g_Wc[wsel + 1], 128, c.tid);
            cp_async_commit();
        }

        float acc[2][8][4];
        gemm_mma_all(As, Bcur, c, acc);

        #pragma unroll
        for (int i = 0; i < 2; ++i)
            #pragma unroll
            for (int j = 0; j < 8; ++j) {
                int row = m0 + c.wm + i * 16 + c.gid;
                int col = wsel * 128 + c.wn + j * 8 + c.tig * 2;
                *(uint32_t*)&g_P[(size_t)row * 512 + col] =
                    pack_h2(acc[i][j][0], acc[i][j][1]);
                *(uint32_t*)&g_P[(size_t)(row + 8) * 512 + col] =
                    pack_h2(acc[i][j][2], acc[i][j][3]);
            }

        if (wsel < 3) {
            cp_async_wait0();
            __syncthreads();
        }
    }
}

// out GEMM.
__global__ void __launch_bounds__(256, 2) out_gemm_f16(float* __restrict__ out)
{
    extern __shared__ __half hsm[];
    __half* As = hsm;
    __half* Bs = hsm + 128 * ASTRH;

    const int m0 = blockIdx.x * 128;
    GemmCtx c;
    c.tid = threadIdx.x;
    c.lane = c.tid & 31;
    int wid = c.tid >> 5;
    c.gid = c.lane >> 2; c.tig = c.lane & 3;
    c.wm = (wid & 3) * 32; c.wn = (wid >> 2) * 64;

    cp_tile_f16(As, &g_O[(size_t)m0 * 128], 128, c.tid);
    cp_tile_f16(Bs, g_Wc[4], 128, c.tid);
    cp_async_commit();
    cp_async_wait0();
    __syncthreads();

    float acc[2][8][4];
    gemm_mma_all(As, Bs, c, acc);

    #pragma unroll
    for (int i = 0; i < 2; ++i)
        #pragma unroll
        for (int j = 0; j < 8; ++j) {
            int row = m0 + c.wm + i * 16 + c.gid;
            int col = c.wn + j * 8 + c.tig * 2;
            *(float2*)&out[(size_t)row * 128 + col] =
                make_float2(acc[i][j][0], acc[i][j][1]);
            *(float2*)&out[(size_t)(row + 8) * 128 + col] =
                make_float2(acc[i][j][2], acc[i][j][3]);
        }
}

// ---------------------------------------------------------------------------
// Kernel 3: fp16 flash attention, full K/V resident, LDSM operand loads.
// ---------------------------------------------------------------------------
__global__ void __launch_bounds__(256) attn_mma_kernel()
{
    const int i    = blockIdx.x;
    const int h    = blockIdx.y;
    const int tid  = threadIdx.x;
    const int wid  = tid >> 5, lane = tid & 31;
    const int gid  = lane >> 2, tig = lane & 3;
    const int wm   = wid * 32;
    const int l15  = lane & 15, lhi = lane >> 4;
    const int l7   = lane & 7,  lq  = lane >> 3;    // 0..3

    __shared__ union {
        __half Qs[256][40];
        struct {
            __half Ks[256][40];             // [t][d]
            __half Vt[32][264];             // [d][t]
        } kv;
    } u;

    const float scale = 0.17677669529663689f;

    // ---- stage Q ----
    #pragma unroll
    for (int l = 0; l < 4; ++l) {
        int fidx = tid + l * 256;
        int r  = fidx >> 2;
        int d8 = (fidx & 3) * 8;
        uint4 v = *(const uint4*)&g_P[(size_t)(i * NN + r) * 512 + h * DHH + d8];
        *(uint4*)&u.Qs[r][d8] = v;
    }
    __syncthreads();

    uint32_t qf[2][2][4];
    #pragma unroll
    for (int ii = 0; ii < 2; ++ii)
        #pragma unroll
        for (int kc = 0; kc < 2; ++kc)
            ldsm_x4(qf[ii][kc], smem_u32(
                &u.Qs[wm + ii * 16 + l15][kc * 16 + lhi * 8]));
    __syncthreads();    // Qs dead

    // ---- stage FULL K (direct) and V (transposed) ----
    #pragma unroll
    for (int l = 0; l < 4; ++l) {
        int fidx = tid + l * 256;
        int r  = fidx >> 2;
        int d8 = (fidx & 3) * 8;
        size_t base = (size_t)(i * NN + r) * 512 + h * DHH + d8;
        uint4 kv4 = *(const uint4*)&g_P[128 + base];
        *(uint4*)&u.kv.Ks[r][d8] = kv4;
        uint4 vv4 = *(const uint4*)&g_P[256 + base];
        __half vh[8];
        *(uint4*)vh = vv4;
        #pragma unroll
        for (int j = 0; j < 8; ++j) u.kv.Vt[d8 + j][r] = vh[j];
    }
    __syncthreads();

    float oacc[2][4][4];
    #pragma unroll
    for (int ii = 0; ii < 2; ++ii)
        #pragma unroll
        for (int dn = 0; dn < 4; ++dn)
            #pragma unroll
            for (int r = 0; r < 4; ++r) oacc[ii][dn][r] = 0.0f;
    float lrun[2][2] = {{0.0f, 0.0f}, {0.0f, 0.0f}};

    for (int kt = 0; kt < 8; ++kt) {
        const int t0 = kt * 32;

        // K fragments: per jt one x4 (d-blocks 0,8,16,24 = kc0 b0/b1, kc1 b0/b1)
        uint32_t kf[4][4];
        #pragma unroll
        for (int jt = 0; jt < 4; ++jt)
            ldsm_x4(kf[jt], smem_u32(&u.kv.Ks[t0 + jt * 8 + l7][lq * 8]));

        // S = Q K^T
        float sacc[2][4][4];
        #pragma unroll
        for (int ii = 0; ii < 2; ++ii)
            #pragma unroll
            for (int jt = 0; jt < 4; ++jt)
                #pragma unroll
                for (int r = 0; r < 4; ++r) sacc[ii][jt][r] = 0.0f;

        #pragma unroll
        for (int jt = 0; jt < 4; ++jt) {
            mma_f16(sacc[0][jt], qf[0][0], &kf[jt][0]);
            mma_f16(sacc[1][jt], qf[1][0], &kf[jt][0]);
            mma_f16(sacc[0][jt], qf[0][1], &kf[jt][2]);
            mma_f16(sacc[1][jt], qf[1][1], &kf[jt][2]);
        }

        // p = exp(s*scale + bias); accumulate l; pack fp16
        uint32_t pa[2][2][4];
        #pragma unroll
        for (int ii = 0; ii < 2; ++ii) {
            int r0 = wm + ii * 16 + gid;
            #pragma unroll
            for (int jt = 0; jt < 4; ++jt) {
                int cc = t0 + jt * 8 + tig * 2;
                float2 b0 = __half22float2(*(const __half2*)&g_bias[h * MM + r0 * NN + cc]);
                float2 b1 = __half22float2(*(const __half2*)&g_bias[h * MM + (r0 + 8) * NN + cc]);
                sacc[ii][jt][0] = __expf(fmaf(sacc[ii][jt][0], scale, b0.x));
                sacc[ii][jt][1] = __expf(fmaf(sacc[ii][jt][1], scale, b0.y));
                sacc[ii][jt][2] = __expf(fmaf(sacc[ii][jt][2], scale, b1.x));
                sacc[ii][jt][3] = __expf(fmaf(sacc[ii][jt][3], scale, b1.y));
            }
            #pragma unroll
            for (int hh = 0; hh < 2; ++hh) {
                float rsum = 0.0f;
                #pragma unroll
                for (int jt = 0; jt < 4; ++jt)
                    rsum += sacc[ii][jt][hh * 2] + sacc[ii][jt][hh * 2 + 1];
                rsum += __shfl_xor_sync(0xffffffffu, rsum, 1);
                rsum += __shfl_xor_sync(0xffffffffu, rsum, 2);
                lrun[ii][hh] += rsum;
            }
            #pragma unroll
            for (int uu = 0; uu < 2; ++uu) {
                pa[ii][uu][0] = pack_h2(sacc[ii][2 * uu][0],     sacc[ii][2 * uu][1]);
                pa[ii][uu][1] = pack_h2(sacc[ii][2 * uu][2],     sacc[ii][2 * uu][3]);
                pa[ii][uu][2] = pack_h2(sacc[ii][2 * uu + 1][0], sacc[ii][2 * uu + 1][1]);
                pa[ii][uu][3] = pack_h2(sacc[ii][2 * uu + 1][2], sacc[ii][2 * uu + 1][3]);
            }
        }

        // V fragments: per dn one x4 (t-blocks 0,8,16,24 = uu0 b0/b1, uu1 b0/b1)
        #pragma unroll
        for (int dn = 0; dn < 4; ++dn) {
            uint32_t vf[4];
            ldsm_x4(vf, smem_u32(&u.kv.Vt[dn * 8 + l7][t0 + lq * 8]));
            mma_f16(oacc[0][dn], pa[0][0], &vf[0]);
            mma_f16(oacc[1][dn], pa[1][0], &vf[0]);
            mma_f16(oacc[0][dn], pa[0][1], &vf[2]);
            mma_f16(oacc[1][dn], pa[1][1], &vf[2]);
        }
    }

    // ---- epilogue: normalize, sigmoid gate, store g_O fp16 ----
    #pragma unroll
    for (int ii = 0; ii < 2; ++ii) {
        float inv0 = 1.0f / lrun[ii][0];
        float inv1 = 1.0f / lrun[ii][1];
        int r0 = wm + ii * 16 + gid;
        #pragma unroll
        for (int dn = 0; dn < 4; ++dn) {
            int col = h * DHH + dn * 8 + tig * 2;
            float2 gv0 = __half22float2(*(const __half2*)&g_P[(size_t)(i * NN + r0) * 512 + 384 + col]);
            float2 gv1 = __half22float2(*(const __half2*)&g_P[(size_t)(i * NN + r0 + 8) * 512 + 384 + col]);
            float o00 = oacc[ii][dn][0] * inv0 / (1.0f + __expf(-gv0.x));
            float o01 = oacc[ii][dn][1] * inv0 / (1.0f + __expf(-gv0.y));
            float o10 = oacc[ii][dn][2] * inv1 / (1.0f + __expf(-gv1.x));
            float o11 = oacc[ii][dn][3] * inv1 / (1.0f + __expf(-gv1.y));
            *(uint32_t*)&g_O[(size_t)(i * NN + r0) * DD + col] = pack_h2(o00, o01);
            *(uint32_t*)&g_O[(size_t)(i * NN + r0 + 8) * DD + col] = pack_h2(o10, o11);
        }
    }
}

// ---------------------------------------------------------------------------
extern "C" void kernel_launch(void* const* d_in, const int* in_sizes, int n_in,
                              void* d_out, int out_size)
{
    const float* x      = (const float*)d_in[0];
    const float* ln_w   = (const float*)d_in[1];
    const float* ln_b   = (const float*)d_in[2];
    const float* bias_w = (const float*)d_in[3];
    const float* q_w    = (const float*)d_in[4];
    const float* k_w    = (const float*)d_in[5];
    const float* v_w    = (const float*)d_in[6];
    const float* g_w    = (const float*)d_in[7];
    const float* o_w    = (const float*)d_in[8];
    float* out = (float*)d_out;

    cudaFuncSetAttribute(proj_gemm_f16,
        cudaFuncAttributeMaxDynamicSharedMemorySize, PROJ_SMEM_BYTES);
    cudaFuncSetAttribute(out_gemm_f16,
        cudaFuncAttributeMaxDynamicSharedMemorySize, OUT_SMEM_BYTES);

    wconv_kernel<<<dim3(16, 5), 256>>>(q_w, k_w, v_w, g_w, o_w);
    ln_bias_kernel<<<MM / 8, 256>>>(x, ln_w, ln_b, bias_w);
    proj_gemm_f16<<<MM / 128, 256, PROJ_SMEM_BYTES>>>();
    attn_mma_kernel<<<dim3(NN, HH), 256>>>();
    out_gemm_f16<<<MM / 128, 256, OUT_SMEM_BYTES>>>(out);
}